// round 1
// baseline (speedup 1.0000x reference)
#include <cuda_runtime.h>

#define N 4096
#define NN (N*N)
#define CIN 64
#define COUT 64
#define RWR 4
#define ITERS 10
#define AMAX_BLOCKS 2048
#define AMAX_THREADS 256

// ---------------- device scratch (static globals: no allocations) ----------------
__device__ float g_L[NN];            // 64MB: dense Laplacian / Jacobi working matrix
__device__ float g_deg[N];
__device__ float g_dinv[N];
__device__ float g_w[N];
__device__ float g_aux[N*CIN];       // U^T x
__device__ float g_outT[N*COUT];     // (n, o)
__device__ float g_G1[CIN*COUT];     // G matrix for w==1, stored [i][o]
__device__ int   g_is64;
__device__ int   g_rotk[ITERS], g_rotl[ITERS];
__device__ float g_rotc[ITERS], g_rots[ITERS];
__device__ float g_pval[AMAX_BLOCKS];
__device__ int   g_pidx[AMAX_BLOCKS];
__device__ int   g_spec[N];
__device__ int   g_nspec;
__device__ unsigned g_done;

__device__ __forceinline__ int edge_at(const int* e, int j) {
    // int64 little-endian: value lives in the low word (values < 4096, nonneg)
    return g_is64 ? e[2*j] : e[j];
}

// ---------------- init: zero deg, detect edge dtype ----------------
__global__ void k_init(const int* e) {
    int t = blockIdx.x*blockDim.x + threadIdx.x;
    if (t < N) g_deg[t] = 0.0f;
    if (t == 0) {
        int nz = 0;
        for (int j = 1; j < 512; j += 2) nz |= (e[j] != 0);
        g_is64 = nz ? 0 : 1;   // int64 data has zero high words
        g_nspec = 0;
        g_done = 0;
    }
}

__global__ void k_deg(const int* e, int E) {
    for (int j = blockIdx.x*blockDim.x + threadIdx.x; j < E; j += gridDim.x*blockDim.x) {
        atomicAdd(&g_deg[edge_at(e, j)], 1.0f);
    }
}

__global__ void k_dinv() {
    int t = blockIdx.x*blockDim.x + threadIdx.x;
    if (t < N) {
        float d = g_deg[t];
        g_dinv[t] = (d > 0.0f) ? __fdiv_rn(1.0f, __fsqrt_rn(d)) : 0.0f;
    }
}

__global__ void k_zeroL() {
    float4* p = (float4*)g_L;
    float4 z = make_float4(0.f, 0.f, 0.f, 0.f);
    for (int t = blockIdx.x*blockDim.x + threadIdx.x; t < NN/4; t += gridDim.x*blockDim.x)
        p[t] = z;
}

__global__ void k_scatter(const int* e, int E) {
    for (int j = blockIdx.x*blockDim.x + threadIdx.x; j < E; j += gridDim.x*blockDim.x) {
        int r = edge_at(e, j);
        int c = edge_at(e, E + j);
        atomicAdd(&g_L[r*N + c], 1.0f);   // A counts (exact small ints)
    }
}

// L[i][j] = (i==j) - (dinv_i * A_ij) * dinv_j   (reference op order, forced round-to-nearest)
__global__ void k_transform() {
    float4* p = (float4*)g_L;
    const float4* dv4 = (const float4*)g_dinv;
    for (int t4 = blockIdx.x*blockDim.x + threadIdx.x; t4 < NN/4; t4 += gridDim.x*blockDim.x) {
        int base = t4*4;
        int i = base >> 12;
        int j = base & (N-1);
        float di = g_dinv[i];
        float4 cnt = p[t4];
        float4 dj = dv4[t4 & (N/4 - 1)];
        float4 o;
        o.x = __fsub_rn((i==j  )?1.0f:0.0f, __fmul_rn(__fmul_rn(di, cnt.x), dj.x));
        o.y = __fsub_rn((i==j+1)?1.0f:0.0f, __fmul_rn(__fmul_rn(di, cnt.y), dj.y));
        o.z = __fsub_rn((i==j+2)?1.0f:0.0f, __fmul_rn(__fmul_rn(di, cnt.z), dj.z));
        o.w = __fsub_rn((i==j+3)?1.0f:0.0f, __fmul_rn(__fmul_rn(di, cnt.w), dj.w));
        p[t4] = o;
    }
}

// ---------------- argmax over strict upper triangle, fused final reduction + rotation params ----------------
__global__ void k_amax(int it) {
    const float4* p = (const float4*)g_L;
    int tid = threadIdx.x;
    float best = -1.0f; int bidx = 0x7FFFFFFF;
    for (int t4 = blockIdx.x*blockDim.x + tid; t4 < NN/4; t4 += gridDim.x*blockDim.x) {
        int base = t4*4;
        int i = base >> 12, j = base & (N-1);
        float4 v = p[t4];
        float a;
        a = fabsf(v.x); if (j+0 > i && (a > best || (a == best && base+0 < bidx))) { best = a; bidx = base+0; }
        a = fabsf(v.y); if (j+1 > i && (a > best || (a == best && base+1 < bidx))) { best = a; bidx = base+1; }
        a = fabsf(v.z); if (j+2 > i && (a > best || (a == best && base+2 < bidx))) { best = a; bidx = base+2; }
        a = fabsf(v.w); if (j+3 > i && (a > best || (a == best && base+3 < bidx))) { best = a; bidx = base+3; }
    }
    __shared__ float sv[AMAX_THREADS];
    __shared__ int   si[AMAX_THREADS];
    sv[tid] = best; si[tid] = bidx;
    __syncthreads();
    for (int off = AMAX_THREADS/2; off > 0; off >>= 1) {
        if (tid < off) {
            float v2 = sv[tid+off]; int i2 = si[tid+off];
            if (v2 > sv[tid] || (v2 == sv[tid] && i2 < si[tid])) { sv[tid] = v2; si[tid] = i2; }
        }
        __syncthreads();
    }
    __shared__ bool isLast;
    if (tid == 0) {
        g_pval[blockIdx.x] = sv[0];
        g_pidx[blockIdx.x] = si[0];
        __threadfence();
        unsigned d = atomicAdd(&g_done, 1u);
        isLast = (d == gridDim.x - 1);
    }
    __syncthreads();
    if (!isLast) return;

    best = -1.0f; bidx = 0x7FFFFFFF;
    for (int b = tid; b < AMAX_BLOCKS; b += AMAX_THREADS) {
        float v2 = *((volatile float*)&g_pval[b]);
        int   i2 = *((volatile int*)&g_pidx[b]);
        if (v2 > best || (v2 == best && i2 < bidx)) { best = v2; bidx = i2; }
    }
    sv[tid] = best; si[tid] = bidx;
    __syncthreads();
    for (int off = AMAX_THREADS/2; off > 0; off >>= 1) {
        if (tid < off) {
            float v2 = sv[tid+off]; int i2 = si[tid+off];
            if (v2 > sv[tid] || (v2 == sv[tid] && i2 < si[tid])) { sv[tid] = v2; si[tid] = i2; }
        }
        __syncthreads();
    }
    if (tid == 0) {
        g_done = 0;
        int idx = si[0];
        int k = idx >> 12, l = idx & (N-1);
        float akl = g_L[k*N + l];
        float akk = g_L[k*N + k];
        float all = g_L[l*N + l];
        float aDiff = __fsub_rn(all, akk);
        float akl_safe   = (akl   == 0.0f) ? 1.0f : akl;
        float aDiff_safe = (aDiff == 0.0f) ? 1.0f : aDiff;
        float phi = __fdiv_rn(aDiff, __fmul_rn(2.0f, akl_safe));
        float t2 = __fdiv_rn(1.0f, __fadd_rn(fabsf(phi),
                     __fsqrt_rn(__fadd_rn(__fmul_rn(phi, phi), 1.0f))));
        if (phi < 0.0f) t2 = -t2;
        float t1 = __fdiv_rn(akl, aDiff_safe);
        float tt = (fabsf(akl) < __fmul_rn(fabsf(aDiff), 1e-36f)) ? t1 : t2;
        float cc = __fdiv_rn(1.0f, __fsqrt_rn(__fadd_rn(__fmul_rn(tt, tt), 1.0f)));
        float ss = __fmul_rn(tt, cc);
        g_rotk[it] = k; g_rotl[it] = l; g_rotc[it] = cc; g_rots[it] = ss;
    }
}

// Two-sided rotation in ONE kernel. For i∉{k,l}: column entries (i,k),(i,l) use originals
// (matches reference col pass), and row entries (k,i),(l,i) also use originals because the
// column pass only modified columns k,l (i∉{k,l}). The 2x2 block is done col-then-row by
// one thread — bitwise identical to the reference sequence.
__global__ void k_rotate(int it) {
    int i = blockIdx.x*blockDim.x + threadIdx.x;
    if (i >= N) return;
    int k = g_rotk[it], l = g_rotl[it];
    float c = g_rotc[it], s = g_rots[it];
    if (i != k && i != l) {
        float ck = g_L[i*N + k], cl = g_L[i*N + l];
        g_L[i*N + k] = __fsub_rn(__fmul_rn(c, ck), __fmul_rn(s, cl));
        g_L[i*N + l] = __fadd_rn(__fmul_rn(s, ck), __fmul_rn(c, cl));
        float rk = g_L[k*N + i], rl = g_L[l*N + i];
        g_L[k*N + i] = __fsub_rn(__fmul_rn(c, rk), __fmul_rn(s, rl));
        g_L[l*N + i] = __fadd_rn(__fmul_rn(s, rk), __fmul_rn(c, rl));
    } else if (i == k) {
        float akk = g_L[k*N + k], akl = g_L[k*N + l];
        float alk = g_L[l*N + k], all = g_L[l*N + l];
        // column pass
        float akk1 = __fsub_rn(__fmul_rn(c, akk), __fmul_rn(s, akl));
        float akl1 = __fadd_rn(__fmul_rn(s, akk), __fmul_rn(c, akl));
        float alk1 = __fsub_rn(__fmul_rn(c, alk), __fmul_rn(s, all));
        float all1 = __fadd_rn(__fmul_rn(s, alk), __fmul_rn(c, all));
        // row pass
        float akk2 = __fsub_rn(__fmul_rn(c, akk1), __fmul_rn(s, alk1));
        float all2 = __fadd_rn(__fmul_rn(s, akl1), __fmul_rn(c, all1));
        g_L[k*N + k] = akk2;
        g_L[l*N + l] = all2;
        g_L[k*N + l] = 0.0f;
        g_L[l*N + k] = 0.0f;
    }
}

// ---------------- eigen-filter application ----------------
__global__ void k_wflag() {
    int t = blockIdx.x*blockDim.x + threadIdx.x;
    if (t < N) {
        float wv = g_L[t*N + t];
        g_w[t] = wv;
        if (wv != 1.0f) {
            int p = atomicAdd(&g_nspec, 1);
            g_spec[p] = t;
        }
    }
}

__device__ __forceinline__ float g_entry(float wv, float hoi,
                                         const float* rw, const float* iw, float cval) {
    float hw = __fmul_rn(hoi, wv);
    float a2 = (hw > 1e-5f) ? 2.0f * atanf(__fdiv_rn(1.0f, hw)) : 2.0f;
    float acc = cval;
#pragma unroll
    for (int r = 0; r < RWR; r++) {
        float th = a2 * (float)(r + 1);
        float sn, cs;
        sincosf(th, &sn, &cs);
        acc += rw[r]*cs - iw[r]*sn;
    }
    return acc;
}

__global__ void k_G1(const float* h, const float* rw, const float* iw, const float* cc) {
    int t = blockIdx.x*blockDim.x + threadIdx.x;
    if (t < COUT*CIN) {
        int o = t >> 6, i = t & 63;
        int oi = o*CIN + i;
        g_G1[i*COUT + o] = g_entry(1.0f, h[oi], rw + oi*RWR, iw + oi*RWR, cc[oi]);
    }
}

__global__ void k_auxinit(const float* x) {
    const float4* xi = (const float4*)x;
    float4* ao = (float4*)g_aux;
    int t = blockIdx.x*blockDim.x + threadIdx.x;
    if (t < N*CIN/4) ao[t] = xi[t];
}

// aux = U^T x = R10^T ... R1^T x  (apply R1^T first)
__global__ void k_auxrot() {
    int o = threadIdx.x;
    for (int t = 0; t < ITERS; t++) {
        int k = g_rotk[t], l = g_rotl[t];
        float c = g_rotc[t], s = g_rots[t];
        float xk = g_aux[k*CIN + o], xl = g_aux[l*CIN + o];
        g_aux[k*CIN + o] = c*xk - s*xl;
        g_aux[l*CIN + o] = s*xk + c*xl;
        __syncthreads();
    }
}

// default path: outT[n][o] = sum_i G1[o][i] * aux[n][i]   (G1 stored [i][o] for coalescing)
__global__ void k_gemm() {
    __shared__ float sa[CIN];
    int n = blockIdx.x, o = threadIdx.x;
    sa[o] = g_aux[n*CIN + o];
    __syncthreads();
    float acc = 0.0f;
#pragma unroll 16
    for (int i = 0; i < CIN; i++)
        acc = fmaf(g_G1[i*COUT + o], sa[i], acc);
    g_outT[n*COUT + o] = acc;
}

// special nodes (w != 1): recompute G(w[n]) on the fly, overwrite their rows
__global__ void k_spec(const float* h, const float* rw, const float* iw, const float* cc) {
    __shared__ float sa[CIN];
    int o = threadIdx.x;
    for (int b = blockIdx.x; b < g_nspec; b += gridDim.x) {
        int n = g_spec[b];
        float wv = g_w[n];
        sa[o] = g_aux[n*CIN + o];
        __syncthreads();
        float acc = 0.0f;
        for (int i = 0; i < CIN; i++) {
            int oi = o*CIN + i;
            float gv = g_entry(wv, h[oi], rw + oi*RWR, iw + oi*RWR, cc[oi]);
            acc = fmaf(gv, sa[i], acc);
        }
        g_outT[n*COUT + o] = acc;
        __syncthreads();
    }
}

// output = U * outT = R1(R2(...(R10 * outT)))  (apply R10 first)
__global__ void k_outrot() {
    int o = threadIdx.x;
    for (int t = ITERS - 1; t >= 0; t--) {
        int k = g_rotk[t], l = g_rotl[t];
        float c = g_rotc[t], s = g_rots[t];
        float vk = g_outT[k*COUT + o], vl = g_outT[l*COUT + o];
        g_outT[k*COUT + o] =  c*vk + s*vl;
        g_outT[l*COUT + o] = -s*vk + c*vl;
        __syncthreads();
    }
}

__global__ void k_final(float* out, const float* bias) {
    int t = blockIdx.x*blockDim.x + threadIdx.x;
    if (t < N*COUT) out[t] = g_outT[t] + bias[t & 63];
}

// ---------------- launch ----------------
extern "C" void kernel_launch(void* const* d_in, const int* in_sizes, int n_in,
                              void* d_out, int out_size) {
    const float* x    = (const float*)d_in[0];
    const int*   e    = (const int*)  d_in[1];
    const float* rw   = (const float*)d_in[2];
    const float* iw   = (const float*)d_in[3];
    const float* h    = (const float*)d_in[4];
    const float* cc   = (const float*)d_in[5];
    const float* bias = (const float*)d_in[6];
    float* out = (float*)d_out;
    int E = in_sizes[1] / 2;   // edge_index element count / 2 (shape (2, E))

    k_init<<<16, 256>>>(e);
    k_deg<<<512, 256>>>(e, E);
    k_dinv<<<16, 256>>>();
    k_zeroL<<<2048, 256>>>();
    k_scatter<<<512, 256>>>(e, E);
    k_transform<<<2048, 256>>>();
    for (int it = 0; it < ITERS; it++) {
        k_amax<<<AMAX_BLOCKS, AMAX_THREADS>>>(it);
        k_rotate<<<16, 256>>>(it);
    }
    k_wflag<<<16, 256>>>();
    k_G1<<<16, 256>>>(h, rw, iw, cc);
    k_auxinit<<<256, 256>>>(x);
    k_auxrot<<<1, 64>>>();
    k_gemm<<<4096, 64>>>();
    k_spec<<<256, 64>>>(h, rw, iw, cc);
    k_outrot<<<1, 64>>>();
    k_final<<<1024, 256>>>(out, bias);
}

// round 4
// speedup vs baseline: 1.1934x; 1.1934x over previous
#include <cuda_runtime.h>

#define N 4096
#define NN (N*N)
#define CIN 64
#define COUT 64
#define RWR 4
#define ITERS 10

// ---------------- device scratch (static globals: no allocations) ----------------
__device__ float g_L[NN];            // 64MB: dense Laplacian / Jacobi working matrix
__device__ float g_deg[N];
__device__ float g_dinv[N];
__device__ float g_w[N];
__device__ float g_aux[N*CIN];       // U^T x
__device__ float g_outT[N*COUT];     // (n, o)
__device__ float g_G1[CIN*COUT];     // G matrix for w==1, stored [i][o]
__device__ int   g_is64;
__device__ int   g_rotk[ITERS], g_rotl[ITERS];
__device__ float g_rotc[ITERS], g_rots[ITERS];
__device__ float g_rowval[N];        // per-row lexmax |a[i][j]|, j>i
__device__ int   g_rowidx[N];        // its column
__device__ int   g_rlist[N];         // rows needing full rescan
__device__ int   g_rn;
__device__ int   g_spec[N];
__device__ int   g_nspec;

__device__ __forceinline__ int edge_at(const int* e, int j) {
    // int64 little-endian: value lives in the low word (values < 4096, nonneg)
    return g_is64 ? e[2*j] : e[j];
}

// lexicographic (val desc, idx asc) compare-and-assign
__device__ __forceinline__ void lexmax(float& bv, int& bi, float v, int i) {
    if (v > bv || (v == bv && i < bi)) { bv = v; bi = i; }
}

// ---------------- init: zero deg, detect edge dtype ----------------
__global__ void k_init(const int* e) {
    int t = blockIdx.x*blockDim.x + threadIdx.x;
    if (t < N) g_deg[t] = 0.0f;
    if (t == 0) {
        int nz = 0;
        for (int j = 1; j < 512; j += 2) nz |= (e[j] != 0);
        g_is64 = nz ? 0 : 1;   // int64 data has zero high words
        g_nspec = 0;
        g_rn = 0;
    }
}

__global__ void k_deg(const int* e, int E) {
    for (int j = blockIdx.x*blockDim.x + threadIdx.x; j < E; j += gridDim.x*blockDim.x) {
        atomicAdd(&g_deg[edge_at(e, j)], 1.0f);
    }
}

__global__ void k_dinv() {
    int t = blockIdx.x*blockDim.x + threadIdx.x;
    if (t < N) {
        float d = g_deg[t];
        g_dinv[t] = (d > 0.0f) ? __fdiv_rn(1.0f, __fsqrt_rn(d)) : 0.0f;
    }
}

__global__ void k_zeroL() {
    float4* p = (float4*)g_L;
    float4 z = make_float4(0.f, 0.f, 0.f, 0.f);
    for (int t = blockIdx.x*blockDim.x + threadIdx.x; t < NN/4; t += gridDim.x*blockDim.x)
        p[t] = z;
}

__global__ void k_scatter(const int* e, int E) {
    for (int j = blockIdx.x*blockDim.x + threadIdx.x; j < E; j += gridDim.x*blockDim.x) {
        int r = edge_at(e, j);
        int c = edge_at(e, E + j);
        atomicAdd(&g_L[r*N + c], 1.0f);   // A counts (exact small ints)
    }
}

// L[i][j] = (i==j) - (dinv_i * A_ij) * dinv_j  (reference op order, forced RN)
// One block per row; fuses the initial per-row strict-upper lexmax.
__global__ void k_transform_rowmax() {
    int i = blockIdx.x;
    int tid = threadIdx.x;
    float di = g_dinv[i];
    float4* row = (float4*)(g_L + (size_t)i*N);
    const float4* dv4 = (const float4*)g_dinv;
    float best = -1.0f; int bcol = 0x7FFFFFFF;
    for (int t4 = tid; t4 < N/4; t4 += blockDim.x) {
        int j = t4*4;
        float4 cnt = row[t4];
        float4 dj = dv4[t4];
        float4 o;
        o.x = __fsub_rn((i==j  )?1.0f:0.0f, __fmul_rn(__fmul_rn(di, cnt.x), dj.x));
        o.y = __fsub_rn((i==j+1)?1.0f:0.0f, __fmul_rn(__fmul_rn(di, cnt.y), dj.y));
        o.z = __fsub_rn((i==j+2)?1.0f:0.0f, __fmul_rn(__fmul_rn(di, cnt.z), dj.z));
        o.w = __fsub_rn((i==j+3)?1.0f:0.0f, __fmul_rn(__fmul_rn(di, cnt.w), dj.w));
        row[t4] = o;
        if (j+0 > i) lexmax(best, bcol, fabsf(o.x), j+0);
        if (j+1 > i) lexmax(best, bcol, fabsf(o.y), j+1);
        if (j+2 > i) lexmax(best, bcol, fabsf(o.z), j+2);
        if (j+3 > i) lexmax(best, bcol, fabsf(o.w), j+3);
    }
    __shared__ float sv[256];
    __shared__ int   si[256];
    sv[tid] = best; si[tid] = bcol;
    __syncthreads();
    for (int off = 128; off > 0; off >>= 1) {
        if (tid < off) {
            float v = sv[tid+off]; int c = si[tid+off];
            if (v > sv[tid] || (v == sv[tid] && c < si[tid])) { sv[tid] = v; si[tid] = c; }
        }
        __syncthreads();
    }
    if (tid == 0) { g_rowval[i] = sv[0]; g_rowidx[i] = si[0]; }
}

// Global argmax over per-row maxima; computes rotation params for iteration `it`.
__global__ void k_argmax(int it) {
    int tid = threadIdx.x;
    float best = -1.0f; int bflat = 0x7FFFFFFF;
    for (int i = tid; i < N; i += blockDim.x) {
        float v = g_rowval[i];
        if (v >= 0.0f) {
            int flat = i*N + g_rowidx[i];
            if (v > best || (v == best && flat < bflat)) { best = v; bflat = flat; }
        }
    }
    __shared__ float sv[256];
    __shared__ int   si[256];
    sv[tid] = best; si[tid] = bflat;
    __syncthreads();
    for (int off = 128; off > 0; off >>= 1) {
        if (tid < off) {
            float v = sv[tid+off]; int f = si[tid+off];
            if (v > sv[tid] || (v == sv[tid] && f < si[tid])) { sv[tid] = v; si[tid] = f; }
        }
        __syncthreads();
    }
    if (tid == 0) {
        int idx = si[0];
        int k = idx >> 12, l = idx & (N-1);
        float akl = g_L[k*N + l];
        float akk = g_L[k*N + k];
        float all = g_L[l*N + l];
        float aDiff = __fsub_rn(all, akk);
        float akl_safe   = (akl   == 0.0f) ? 1.0f : akl;
        float aDiff_safe = (aDiff == 0.0f) ? 1.0f : aDiff;
        float phi = __fdiv_rn(aDiff, __fmul_rn(2.0f, akl_safe));
        float t2 = __fdiv_rn(1.0f, __fadd_rn(fabsf(phi),
                     __fsqrt_rn(__fadd_rn(__fmul_rn(phi, phi), 1.0f))));
        if (phi < 0.0f) t2 = -t2;
        float t1 = __fdiv_rn(akl, aDiff_safe);
        float tt = (fabsf(akl) < __fmul_rn(fabsf(aDiff), 1e-36f)) ? t1 : t2;
        float cc = __fdiv_rn(1.0f, __fsqrt_rn(__fadd_rn(__fmul_rn(tt, tt), 1.0f)));
        float ss = __fmul_rn(tt, cc);
        g_rotk[it] = k; g_rotl[it] = l; g_rotc[it] = cc; g_rots[it] = ss;
        g_rn = 0;    // reset rescan list for the upcoming rotation
    }
}

// Two-sided rotation + incremental rowmax maintenance.
// Bitwise identical matrix arithmetic to the reference col-then-row sequence.
__global__ void k_rotate(int it) {
    int i = blockIdx.x*blockDim.x + threadIdx.x;
    if (i >= N) return;
    int k = g_rotk[it], l = g_rotl[it];
    float c = g_rotc[it], s = g_rots[it];
    if (i != k && i != l) {
        float ck = g_L[i*N + k], cl = g_L[i*N + l];
        float nk = __fsub_rn(__fmul_rn(c, ck), __fmul_rn(s, cl));
        float nl = __fadd_rn(__fmul_rn(s, ck), __fmul_rn(c, cl));
        g_L[i*N + k] = nk;
        g_L[i*N + l] = nl;
        float rk = g_L[k*N + i], rl = g_L[l*N + i];
        g_L[k*N + i] = __fsub_rn(__fmul_rn(c, rk), __fmul_rn(s, rl));
        g_L[l*N + i] = __fadd_rn(__fmul_rn(s, rk), __fmul_rn(c, rl));
        // incremental per-row max of row i
        float bv = g_rowval[i]; int bj = g_rowidx[i];
        if (bj == k || bj == l) {
            int p = atomicAdd(&g_rn, 1);
            g_rlist[p] = i;                 // old max invalidated: full rescan
        } else {
            bool ch = false;
            if (k > i) { float a = fabsf(nk); if (a > bv || (a == bv && k < bj)) { bv = a; bj = k; ch = true; } }
            if (l > i) { float a = fabsf(nl); if (a > bv || (a == bv && l < bj)) { bv = a; bj = l; ch = true; } }
            if (ch) { g_rowval[i] = bv; g_rowidx[i] = bj; }
        }
    } else if (i == k) {
        float akk = g_L[k*N + k], akl = g_L[k*N + l];
        float alk = g_L[l*N + k], all = g_L[l*N + l];
        // column pass
        float akk1 = __fsub_rn(__fmul_rn(c, akk), __fmul_rn(s, akl));
        float akl1 = __fadd_rn(__fmul_rn(s, akk), __fmul_rn(c, akl));
        float alk1 = __fsub_rn(__fmul_rn(c, alk), __fmul_rn(s, all));
        float all1 = __fadd_rn(__fmul_rn(s, alk), __fmul_rn(c, all));
        // row pass
        float akk2 = __fsub_rn(__fmul_rn(c, akk1), __fmul_rn(s, alk1));
        float all2 = __fadd_rn(__fmul_rn(s, akl1), __fmul_rn(c, all1));
        g_L[k*N + k] = akk2;
        g_L[l*N + l] = all2;
        g_L[k*N + l] = 0.0f;
        g_L[l*N + k] = 0.0f;
        int p = atomicAdd(&g_rn, 2);
        g_rlist[p] = k; g_rlist[p+1] = l;   // rows k,l always rescanned
    }
}

// Full rescan of flagged rows (strict upper part only).
__global__ void k_recompute() {
    int tid = threadIdx.x;
    __shared__ float sv[256];
    __shared__ int   si[256];
    int nr = g_rn;
    for (int b = blockIdx.x; b < nr; b += gridDim.x) {
        int i = g_rlist[b];
        const float* row = g_L + (size_t)i*N;
        float best = -1.0f; int bcol = 0x7FFFFFFF;
        for (int j = i + 1 + tid; j < N; j += blockDim.x) {
            float a = fabsf(row[j]);
            if (a > best || (a == best && j < bcol)) { best = a; bcol = j; }
        }
        sv[tid] = best; si[tid] = bcol;
        __syncthreads();
        for (int off = 128; off > 0; off >>= 1) {
            if (tid < off) {
                float v = sv[tid+off]; int cI = si[tid+off];
                if (v > sv[tid] || (v == sv[tid] && cI < si[tid])) { sv[tid] = v; si[tid] = cI; }
            }
            __syncthreads();
        }
        if (tid == 0) { g_rowval[i] = sv[0]; g_rowidx[i] = si[0]; }
        __syncthreads();
    }
}

// ---------------- eigen-filter application ----------------
__global__ void k_wflag() {
    int t = blockIdx.x*blockDim.x + threadIdx.x;
    if (t < N) {
        float wv = g_L[t*N + t];
        g_w[t] = wv;
        if (wv != 1.0f) {
            int p = atomicAdd(&g_nspec, 1);
            g_spec[p] = t;
        }
    }
}

__device__ __forceinline__ float g_entry(float wv, float hoi,
                                         const float* rw, const float* iw, float cval) {
    float hw = __fmul_rn(hoi, wv);
    float a2 = (hw > 1e-5f) ? 2.0f * atanf(__fdiv_rn(1.0f, hw)) : 2.0f;
    float acc = cval;
#pragma unroll
    for (int r = 0; r < RWR; r++) {
        float th = a2 * (float)(r + 1);
        float sn, cs;
        sincosf(th, &sn, &cs);
        acc += rw[r]*cs - iw[r]*sn;
    }
    return acc;
}

__global__ void k_G1(const float* h, const float* rw, const float* iw, const float* cc) {
    int t = blockIdx.x*blockDim.x + threadIdx.x;
    if (t < COUT*CIN) {
        int o = t >> 6, i = t & 63;
        int oi = o*CIN + i;
        g_G1[i*COUT + o] = g_entry(1.0f, h[oi], rw + oi*RWR, iw + oi*RWR, cc[oi]);
    }
}

__global__ void k_auxinit(const float* x) {
    const float4* xi = (const float4*)x;
    float4* ao = (float4*)g_aux;
    int t = blockIdx.x*blockDim.x + threadIdx.x;
    if (t < N*CIN/4) ao[t] = xi[t];
}

// aux = U^T x = R10^T ... R1^T x  (apply R1^T first)
__global__ void k_auxrot() {
    int o = threadIdx.x;
    for (int t = 0; t < ITERS; t++) {
        int k = g_rotk[t], l = g_rotl[t];
        float c = g_rotc[t], s = g_rots[t];
        float xk = g_aux[k*CIN + o], xl = g_aux[l*CIN + o];
        g_aux[k*CIN + o] = c*xk - s*xl;
        g_aux[l*CIN + o] = s*xk + c*xl;
        __syncthreads();
    }
}

// default path: outT[n][o] = sum_i G1[o][i] * aux[n][i]   (G1 stored [i][o])
__global__ void k_gemm() {
    __shared__ float sa[CIN];
    int n = blockIdx.x, o = threadIdx.x;
    sa[o] = g_aux[n*CIN + o];
    __syncthreads();
    float acc = 0.0f;
#pragma unroll 16
    for (int i = 0; i < CIN; i++)
        acc = fmaf(g_G1[i*COUT + o], sa[i], acc);
    g_outT[n*COUT + o] = acc;
}

// special nodes (w != 1): recompute G(w[n]) on the fly, overwrite their rows
__global__ void k_spec(const float* h, const float* rw, const float* iw, const float* cc) {
    __shared__ float sa[CIN];
    int o = threadIdx.x;
    for (int b = blockIdx.x; b < g_nspec; b += gridDim.x) {
        int n = g_spec[b];
        float wv = g_w[n];
        sa[o] = g_aux[n*CIN + o];
        __syncthreads();
        float acc = 0.0f;
        for (int i = 0; i < CIN; i++) {
            int oi = o*CIN + i;
            float gv = g_entry(wv, h[oi], rw + oi*RWR, iw + oi*RWR, cc[oi]);
            acc = fmaf(gv, sa[i], acc);
        }
        g_outT[n*COUT + o] = acc;
        __syncthreads();
    }
}

// output = U * outT = R1(R2(...(R10 * outT)))  (apply R10 first)
__global__ void k_outrot() {
    int o = threadIdx.x;
    for (int t = ITERS - 1; t >= 0; t--) {
        int k = g_rotk[t], l = g_rotl[t];
        float c = g_rotc[t], s = g_rots[t];
        float vk = g_outT[k*COUT + o], vl = g_outT[l*COUT + o];
        g_outT[k*COUT + o] =  c*vk + s*vl;
        g_outT[l*COUT + o] = -s*vk + c*vl;
        __syncthreads();
    }
}

__global__ void k_final(float* out, const float* bias) {
    int t = blockIdx.x*blockDim.x + threadIdx.x;
    if (t < N*COUT) out[t] = g_outT[t] + bias[t & 63];
}

// ---------------- launch ----------------
extern "C" void kernel_launch(void* const* d_in, const int* in_sizes, int n_in,
                              void* d_out, int out_size) {
    const float* x    = (const float*)d_in[0];
    const int*   e    = (const int*)  d_in[1];
    const float* rw   = (const float*)d_in[2];
    const float* iw   = (const float*)d_in[3];
    const float* h    = (const float*)d_in[4];
    const float* cc   = (const float*)d_in[5];
    const float* bias = (const float*)d_in[6];
    float* out = (float*)d_out;
    int E = in_sizes[1] / 2;   // edge_index shape (2, E)

    k_init<<<16, 256>>>(e);
    k_deg<<<512, 256>>>(e, E);
    k_dinv<<<16, 256>>>();
    k_zeroL<<<2048, 256>>>();
    k_scatter<<<512, 256>>>(e, E);
    k_transform_rowmax<<<4096, 256>>>();
    k_argmax<<<1, 256>>>(0);
    for (int it = 0; it < ITERS; it++) {
        k_rotate<<<16, 256>>>(it);
        if (it + 1 < ITERS) {
            k_recompute<<<256, 256>>>();
            k_argmax<<<1, 256>>>(it + 1);
        }
    }
    k_wflag<<<16, 256>>>();
    k_G1<<<16, 256>>>(h, rw, iw, cc);
    k_auxinit<<<256, 256>>>(x);
    k_auxrot<<<1, 64>>>();
    k_gemm<<<4096, 64>>>();
    k_spec<<<256, 64>>>(h, rw, iw, cc);
    k_outrot<<<1, 64>>>();
    k_final<<<1024, 256>>>(out, bias);
}